// round 15
// baseline (speedup 1.0000x reference)
#include <cuda_runtime.h>
#include <cuda_bf16.h>
#include <math.h>
#include <stdint.h>

#define B_  2
#define N_  1024
#define T_  8
#define D_  128
#define H_  4
#define E_  8192
#define M_  16384
#define MAXDEG 128

// ---------------- scratch (device globals) ----------------------------------
__device__ __align__(256) float g_xlr[(size_t)M_ * 1024];   // [xl(512)|xr(512)]
__device__ __align__(256) float g_qkv[(size_t)M_ * 384];
__device__ __align__(256) float g_attno[(size_t)M_ * 128];
__device__ __align__(256) float g_x1[(size_t)M_ * 128];
__device__ __align__(256) float g_hid[(size_t)M_ * 512];
__device__ __align__(256) float g_cat[(size_t)M_ * 256];    // [x_sp | x_tp]
// packed tf32 weights, [n][k] layout (pre-rounded via cvt.rna)
__device__ __align__(256) float g_Bxq[1408 * 128];          // [Wl|Wr|Wqkv]
__device__ __align__(256) float g_bias_xq[1408];            // [0(1024) | in_b(384)]
__device__ __align__(256) float g_Bout[128 * 128];
__device__ __align__(256) float g_Bffn1[512 * 128];
__device__ __align__(256) float g_Bffn2[128 * 512];
__device__ __align__(256) float g_Bfus[128 * 256];
// CSR
__device__ int g_deg[N_];
__device__ int g_csr[N_ * MAXDEG];

// ---------------- helpers ------------------------------------------------------
__device__ __forceinline__ float warp_sum(float v) {
#pragma unroll
    for (int o = 16; o; o >>= 1) v += __shfl_xor_sync(0xFFFFFFFFu, v, o);
    return v;
}
__device__ __forceinline__ uint32_t smem_u32(const void* p) {
    uint32_t a;
    asm("{ .reg .u64 t; cvta.to.shared.u64 t, %1; cvt.u32.u64 %0, t; }"
        : "=r"(a) : "l"(p));
    return a;
}
#define CP16(dst, src) \
    asm volatile("cp.async.cg.shared.global [%0], [%1], 16;" :: "r"(dst), "l"(src))
#define CVT_TF32(u, f) asm("cvt.rna.tf32.f32 %0, %1;" : "=r"(u) : "f"(f))

__device__ __forceinline__ void mma_tf32(float c[4], const uint32_t a[4],
                                         const uint32_t b[2]) {
    asm volatile(
        "mma.sync.aligned.m16n8k8.row.col.f32.tf32.tf32.f32 "
        "{%0,%1,%2,%3}, {%4,%5,%6,%7}, {%8,%9}, {%0,%1,%2,%3};"
        : "+f"(c[0]), "+f"(c[1]), "+f"(c[2]), "+f"(c[3])
        : "r"(a[0]), "r"(a[1]), "r"(a[2]), "r"(a[3]), "r"(b[0]), "r"(b[1]));
}

__device__ __forceinline__ float4 ln_compute(float4 v, const float* g, const float* b,
                                             int lane) {
    float mean = warp_sum(v.x + v.y + v.z + v.w) * (1.f / 128.f);
    float4 c = make_float4(v.x - mean, v.y - mean, v.z - mean, v.w - mean);
    float var = warp_sum(c.x * c.x + c.y * c.y + c.z * c.z + c.w * c.w) * (1.f / 128.f);
    float rs = rsqrtf(var + 1e-5f);
    float4 gv = *(const float4*)&g[lane * 4];
    float4 bv = *(const float4*)&b[lane * 4];
    return make_float4(c.x * rs * gv.x + bv.x, c.y * rs * gv.y + bv.y,
                       c.z * rs * gv.z + bv.z, c.w * rs * gv.w + bv.w);
}

// ---------------- CSR ------------------------------------------------------------
__global__ void k_csr0() {
    int i = blockIdx.x * blockDim.x + threadIdx.x;
    if (i < N_) { g_deg[i] = 1; g_csr[i * MAXDEG] = i; }   // self loop
}
__global__ void k_scatter(const int* __restrict__ edges) {
    int e = blockIdx.x * blockDim.x + threadIdx.x;
    if (e >= E_) return;
    int s = edges[e], d = edges[E_ + e];
    int pos = atomicAdd(&g_deg[d], 1);
    if (pos < MAXDEG) g_csr[d * MAXDEG + pos] = s;
}

// ---------------- weight packing (split) -----------------------------------------
__global__ void k_packA(const float* wl, const float* wr, const float* inw) {
    int job = blockIdx.y;
    int idx = blockIdx.x * 256 + threadIdx.x;
    const float* W; int K = 128, Nw, coff = 0;
    switch (job) {
        case 0: W = wl;  Nw = 512; break;
        case 1: W = wr;  Nw = 512; coff = 512; break;
        default:W = inw; Nw = 384; coff = 1024; break;
    }
    if (idx >= K * Nw) return;
    int k = idx / Nw, n = idx % Nw;
    uint32_t u;
    CVT_TF32(u, W[idx]);
    g_Bxq[(size_t)(coff + n) * K + k] = __uint_as_float(u);
}
__global__ void k_packB(const float* outw, const float* f1w, const float* f2w,
                        const float* fw, const float* in_b) {
    int job = blockIdx.y;
    int idx = blockIdx.x * 256 + threadIdx.x;
    if (job == 4) {
        if (idx < 1408) g_bias_xq[idx] = (idx < 1024) ? 0.f : in_b[idx - 1024];
        return;
    }
    const float* W; float* Bo; int K, Nw;
    switch (job) {
        case 0: W = outw; Bo = g_Bout;  K = 128; Nw = 128; break;
        case 1: W = f1w;  Bo = g_Bffn1; K = 128; Nw = 512; break;
        case 2: W = f2w;  Bo = g_Bffn2; K = 512; Nw = 128; break;
        default:W = fw;   Bo = g_Bfus;  K = 256; Nw = 128; break;
    }
    if (idx >= K * Nw) return;
    int k = idx / Nw, n = idx % Nw;
    uint32_t u;
    CVT_TF32(u, W[idx]);
    Bo[(size_t)n * K + k] = __uint_as_float(u);
}

// ---------------- tf32 mma.sync GEMM, 4-stage pipeline, templated epilogue --------
// MODE 1: +bias -> C1 ; MODE 2: +bias+GELU -> C1
// MODE 4/5: +bias, LN(xres + C) -> C1
// MODE 6: sigmoid gate; LN(g*xsp+(1-g)*xtp+xres) -> C1
#define KP 20
#define APLANE (64 * KP)
#define BPLANE (128 * KP)
#define NSTAGE 4
#define SMEMSZ ((APLANE + BPLANE) * NSTAGE * 4)

template<int MODE>
__global__ void __launch_bounds__(256, 3) hgemm(
        const float* __restrict__ A, const float* __restrict__ Bp,
        const float* __restrict__ bias,
        float* __restrict__ C1, int s1,
        float* __restrict__ C2,
        int K,
        const float* __restrict__ xres,
        const float* __restrict__ lng, const float* __restrict__ lnb) {
    extern __shared__ float sm[];
    float* sA = sm;
    float* sB = sm + NSTAGE * APLANE;
    int tid = threadIdx.x, wid = tid >> 5, lane = tid & 31;
    int wm = wid >> 2, wn = wid & 3;
    int rowBase = blockIdx.y * 64, colBase = blockIdx.x * 128;
    int nk = K >> 4;

    float acc[2][4][4];
#pragma unroll
    for (int i = 0; i < 2; i++)
#pragma unroll
        for (int j = 0; j < 4; j++)
#pragma unroll
            for (int q = 0; q < 4; q++) acc[i][j][q] = 0.f;

    int ar = tid >> 2, aq = tid & 3;
    int br = tid >> 1, bq = (tid & 1) * 2;
    const char* Asrc = (const char*)(A + (size_t)(rowBase + ar) * K + aq * 4);
    const char* Bsrc = (const char*)(Bp + (size_t)(colBase + br) * K + bq * 4);
    uint32_t dA = smem_u32(sA) + (uint32_t)(ar * KP + aq * 4) * 4;
    uint32_t dB = smem_u32(sB) + (uint32_t)(br * KP + bq * 4) * 4;

    auto ld = [&](int kt, int buf) {
        CP16(dA + buf * (APLANE * 4), Asrc + (size_t)kt * 64);
        CP16(dB + buf * (BPLANE * 4), Bsrc + (size_t)kt * 64);
        CP16(dB + buf * (BPLANE * 4) + 16, Bsrc + (size_t)kt * 64 + 16);
        asm volatile("cp.async.commit_group;" ::: "memory");
    };

    ld(0, 0); ld(1, 1); ld(2, 2);

    int fr = lane >> 2, fq = lane & 3;
    const float* awp = sA + (wm * 32 + fr) * KP + fq;
    const float* bwp = sB + (wn * 32 + fr) * KP + fq;

    for (int kt = 0; kt < nk; kt++) {
        int buf = kt & 3;
        if (kt + 2 < nk)      asm volatile("cp.async.wait_group 2;" ::: "memory");
        else if (kt + 1 < nk) asm volatile("cp.async.wait_group 1;" ::: "memory");
        else                  asm volatile("cp.async.wait_group 0;" ::: "memory");
        __syncthreads();
        if (kt + 3 < nk) ld(kt + 3, (kt + 3) & 3);

        const float* aw = awp + buf * APLANE;
        const float* bw = bwp + buf * BPLANE;
#pragma unroll
        for (int k8 = 0; k8 < 2; k8++) {
            uint32_t ua[2][4], ub[4][2];
#pragma unroll
            for (int mi = 0; mi < 2; mi++) {
                const float* ap = aw + mi * (16 * KP) + k8 * 8;
                CVT_TF32(ua[mi][0], ap[0]);
                CVT_TF32(ua[mi][1], ap[8 * KP]);
                CVT_TF32(ua[mi][2], ap[4]);
                CVT_TF32(ua[mi][3], ap[8 * KP + 4]);
            }
#pragma unroll
            for (int ni = 0; ni < 4; ni++) {
                const float* bp = bw + ni * (8 * KP) + k8 * 8;
                ub[ni][0] = __float_as_uint(bp[0]);
                ub[ni][1] = __float_as_uint(bp[4]);
            }
#pragma unroll
            for (int mi = 0; mi < 2; mi++)
#pragma unroll
                for (int ni = 0; ni < 4; ni++)
                    mma_tf32(acc[mi][ni], ua[mi], ub[ni]);
        }
    }

    int fc2 = (lane & 3) * 2;
    if (MODE == 1 || MODE == 2) {
#pragma unroll
        for (int mi = 0; mi < 2; mi++) {
            int r0 = rowBase + wm * 32 + mi * 16 + fr;
#pragma unroll
            for (int ni = 0; ni < 4; ni++) {
                int col = colBase + wn * 32 + ni * 8 + fc2;
                float b0 = bias[col], b1 = bias[col + 1];
                float v[4] = {acc[mi][ni][0] + b0, acc[mi][ni][1] + b1,
                              acc[mi][ni][2] + b0, acc[mi][ni][3] + b1};
                if (MODE == 2) {
#pragma unroll
                    for (int q = 0; q < 4; q++)
                        v[q] = 0.5f * v[q] * (1.f + erff(v[q] * 0.70710678118654752f));
                }
                *(float2*)&C1[(size_t)r0 * s1 + col]       = make_float2(v[0], v[1]);
                *(float2*)&C1[(size_t)(r0 + 8) * s1 + col] = make_float2(v[2], v[3]);
            }
        }
    } else {
        float* st = sm;
        __syncthreads();
#pragma unroll
        for (int mi = 0; mi < 2; mi++) {
            int rl = wm * 32 + mi * 16 + fr;
#pragma unroll
            for (int ni = 0; ni < 4; ni++) {
                int col = wn * 32 + ni * 8 + fc2;
                float b0 = bias[col], b1 = bias[col + 1];
                float v0 = acc[mi][ni][0] + b0, v1 = acc[mi][ni][1] + b1;
                float v2 = acc[mi][ni][2] + b0, v3 = acc[mi][ni][3] + b1;
                if (MODE == 6) {
                    v0 = 1.f / (1.f + __expf(-v0)); v1 = 1.f / (1.f + __expf(-v1));
                    v2 = 1.f / (1.f + __expf(-v2)); v3 = 1.f / (1.f + __expf(-v3));
                }
                *(float2*)&st[rl * 128 + col]       = make_float2(v0, v1);
                *(float2*)&st[(rl + 8) * 128 + col] = make_float2(v2, v3);
            }
        }
        __syncthreads();
#pragma unroll
        for (int r = 0; r < 8; r++) {
            int rl = wid * 8 + r;
            int grow = rowBase + rl;
            float4 cv = ((const float4*)(st + rl * 128))[lane];
            float4 v;
            if (MODE == 4 || MODE == 5) {
                float4 xv = *(const float4*)&xres[(size_t)grow * 128 + lane * 4];
                v = make_float4(cv.x + xv.x, cv.y + xv.y, cv.z + xv.z, cv.w + xv.w);
            } else {
                float4 xsp = *(const float4*)&C2[(size_t)grow * 256 + lane * 4];
                float4 xtp = *(const float4*)&C2[(size_t)grow * 256 + 128 + lane * 4];
                float4 xv  = *(const float4*)&xres[(size_t)grow * 128 + lane * 4];
                v = make_float4(cv.x * xsp.x + (1.f - cv.x) * xtp.x + xv.x,
                                cv.y * xsp.y + (1.f - cv.y) * xtp.y + xv.y,
                                cv.z * xsp.z + (1.f - cv.z) * xtp.z + xv.z,
                                cv.w * xsp.w + (1.f - cv.w) * xtp.w + xv.w);
            }
            float4 r4 = ln_compute(v, lng, lnb, lane);
            *(float4*)&C1[(size_t)grow * s1 + lane * 4] = r4;
        }
    }
}

// ---------------- fused GAT (online softmax, dst-centric) --------------------------
__global__ void k_gat(const float* __restrict__ att, const float* __restrict__ gat_b,
                      const float* __restrict__ lg, const float* __restrict__ lb) {
    int w = (blockIdx.x * blockDim.x + threadIdx.x) >> 5;
    int lane = threadIdx.x & 31;
    if (w >= M_) return;
    int bn = w >> 3;
    int n = bn & (N_ - 1);
    int b = bn >> 10;
    int t = w & 7;

    const float4* xr4 = (const float4*)(g_xlr + (size_t)w * 1024 + 512);
    float4 xr[4], av[4];
#pragma unroll
    for (int h = 0; h < 4; h++) {
        xr[h] = xr4[h * 32 + lane];
        av[h] = ((const float4*)att)[h * 32 + lane];
    }
    float4 acc[4];
#pragma unroll
    for (int h = 0; h < 4; h++) acc[h] = make_float4(0.f, 0.f, 0.f, 0.f);
    float m[4] = {-INFINITY, -INFINITY, -INFINITY, -INFINITY};
    float s[4] = {0.f, 0.f, 0.f, 0.f};

    int deg = g_deg[n];
    if (deg > MAXDEG) deg = MAXDEG;
    const int* clist = g_csr + n * MAXDEG;

    for (int i = 0; i < deg; i++) {
        int src = clist[i];
        const float4* xl4 = (const float4*)(g_xlr + ((size_t)((b * N_ + src) * T_ + t)) * 1024);
        float4 xl[4];
        float lgt[4];
#pragma unroll
        for (int h = 0; h < 4; h++) {
            float4 a = xl4[h * 32 + lane];
            xl[h] = a;
            float v0 = a.x + xr[h].x; v0 = v0 > 0.f ? v0 : 0.2f * v0;
            float v1 = a.y + xr[h].y; v1 = v1 > 0.f ? v1 : 0.2f * v1;
            float v2 = a.z + xr[h].z; v2 = v2 > 0.f ? v2 : 0.2f * v2;
            float v3 = a.w + xr[h].w; v3 = v3 > 0.f ? v3 : 0.2f * v3;
            lgt[h] = warp_sum(av[h].x * v0 + av[h].y * v1 + av[h].z * v2 + av[h].w * v3);
        }
#pragma unroll
        for (int h = 0; h < 4; h++) {
            float nm = fmaxf(m[h], lgt[h]);
            float e0 = __expf(m[h] - nm);
            float e1 = __expf(lgt[h] - nm);
            s[h] = s[h] * e0 + e1;
            acc[h].x = acc[h].x * e0 + e1 * xl[h].x;
            acc[h].y = acc[h].y * e0 + e1 * xl[h].y;
            acc[h].z = acc[h].z * e0 + e1 * xl[h].z;
            acc[h].w = acc[h].w * e0 + e1 * xl[h].w;
            m[h] = nm;
        }
    }

    float4 o = make_float4(0.f, 0.f, 0.f, 0.f);
#pragma unroll
    for (int h = 0; h < 4; h++) {
        float r = 0.25f / s[h];
        o.x += acc[h].x * r; o.y += acc[h].y * r;
        o.z += acc[h].z * r; o.w += acc[h].w * r;
    }
    float4 gb = *(const float4*)&gat_b[lane * 4];
    o.x += gb.x; o.y += gb.y; o.z += gb.z; o.w += gb.w;

    float4 r4 = ln_compute(o, lg, lb, lane);
    *(float4*)&g_cat[(size_t)w * 256 + lane * 4] = r4;
}

// ---------------- temporal attention ------------------------------------------------
__global__ void k_attn() {
    int w = blockIdx.x * 4 + (threadIdx.x >> 5);
    int lane = threadIdx.x & 31;
    if (w >= (B_ * N_) * H_) return;
    int bn = w >> 2;
    int h = w & 3;
    float q[8], k[8], v[8];
#pragma unroll
    for (int t = 0; t < 8; t++) {
        size_t base = ((size_t)bn * 8 + t) * 384 + h * 32 + lane;
        q[t] = g_qkv[base];
        k[t] = g_qkv[base + 128];
        v[t] = g_qkv[base + 256];
    }
    const float scale = 0.17677669529663687f;
#pragma unroll
    for (int t = 0; t < 8; t++) {
        float sc[8];
#pragma unroll
        for (int s = 0; s < 8; s++) sc[s] = warp_sum(q[t] * k[s]) * scale;
        float mx = sc[0];
#pragma unroll
        for (int s = 1; s < 8; s++) mx = fmaxf(mx, sc[s]);
        float den = 0.f;
#pragma unroll
        for (int s = 0; s < 8; s++) { sc[s] = __expf(sc[s] - mx); den += sc[s]; }
        float inv = 1.f / den;
        float o = 0.f;
#pragma unroll
        for (int s = 0; s < 8; s++) o += sc[s] * v[s];
        g_attno[((size_t)bn * 8 + t) * D_ + h * 32 + lane] = o * inv;
    }
}

// ---------------- launch ---------------------------------------------------------------
extern "C" void kernel_launch(void* const* d_in, const int* in_sizes, int n_in,
                              void* d_out, int out_size) {
    const float* x      = (const float*)d_in[0];
    const int*   edges  = (const int*)  d_in[1];
    const float* gat_att= (const float*)d_in[4];
    const float* gat_b  = (const float*)d_in[5];
    const float* in_b   = (const float*)d_in[7];
    const float* out_b  = (const float*)d_in[9];
    const float* ffn_b1 = (const float*)d_in[11];
    const float* ffn_b2 = (const float*)d_in[13];
    const float* fus_b  = (const float*)d_in[15];
    const float* lns_g  = (const float*)d_in[16];
    const float* lns_b  = (const float*)d_in[17];
    const float* lnt1_g = (const float*)d_in[18];
    const float* lnt1_b = (const float*)d_in[19];
    const float* lnt2_g = (const float*)d_in[20];
    const float* lnt2_b = (const float*)d_in[21];
    const float* lnf_g  = (const float*)d_in[22];
    const float* lnf_b  = (const float*)d_in[23];
    float* out = (float*)d_out;

    float *p_xlr, *p_qkv, *p_attno, *p_x1, *p_hid, *p_cat;
    float *p_bxq, *p_Bxq, *p_Bout, *p_Bffn1, *p_Bffn2, *p_Bfus;
    cudaGetSymbolAddress((void**)&p_xlr,   g_xlr);
    cudaGetSymbolAddress((void**)&p_qkv,   g_qkv);
    cudaGetSymbolAddress((void**)&p_attno, g_attno);
    cudaGetSymbolAddress((void**)&p_x1,    g_x1);
    cudaGetSymbolAddress((void**)&p_hid,   g_hid);
    cudaGetSymbolAddress((void**)&p_cat,   g_cat);
    cudaGetSymbolAddress((void**)&p_bxq,   g_bias_xq);
    cudaGetSymbolAddress((void**)&p_Bxq,   g_Bxq);
    cudaGetSymbolAddress((void**)&p_Bout,  g_Bout);
    cudaGetSymbolAddress((void**)&p_Bffn1, g_Bffn1);
    cudaGetSymbolAddress((void**)&p_Bffn2, g_Bffn2);
    cudaGetSymbolAddress((void**)&p_Bfus,  g_Bfus);

    cudaFuncSetAttribute(hgemm<1>, cudaFuncAttributeMaxDynamicSharedMemorySize, SMEMSZ);
    cudaFuncSetAttribute(hgemm<2>, cudaFuncAttributeMaxDynamicSharedMemorySize, SMEMSZ);
    cudaFuncSetAttribute(hgemm<4>, cudaFuncAttributeMaxDynamicSharedMemorySize, SMEMSZ);
    cudaFuncSetAttribute(hgemm<5>, cudaFuncAttributeMaxDynamicSharedMemorySize, SMEMSZ);
    cudaFuncSetAttribute(hgemm<6>, cudaFuncAttributeMaxDynamicSharedMemorySize, SMEMSZ);

    static cudaStream_t s1 = nullptr, s2 = nullptr;
    static cudaEvent_t evRoot = nullptr, evFork = nullptr, evJoin = nullptr, evPackB = nullptr;
    if (s1 == nullptr) {
        cudaStreamCreateWithFlags(&s1, cudaStreamNonBlocking);
        cudaStreamCreateWithFlags(&s2, cudaStreamNonBlocking);
        cudaEventCreateWithFlags(&evRoot, cudaEventDisableTiming);
        cudaEventCreateWithFlags(&evFork, cudaEventDisableTiming);
        cudaEventCreateWithFlags(&evJoin, cudaEventDisableTiming);
        cudaEventCreateWithFlags(&evPackB, cudaEventDisableTiming);
    }

    // root fork: s1 and s2 join the capture FIRST (required for valid capture)
    cudaEventRecord(evRoot, 0);
    cudaStreamWaitEvent(s1, evRoot, 0);
    cudaStreamWaitEvent(s2, evRoot, 0);

    // s1: CSR build (needed only by k_gat later on s1)
    k_csr0<<<4, 256, 0, s1>>>();
    k_scatter<<<E_ / 256, 256, 0, s1>>>(edges);
    // s2: late weights + bias
    k_packB<<<dim3(256, 5), 256, 0, s2>>>((const float*)d_in[8], (const float*)d_in[10],
                                          (const float*)d_in[12], (const float*)d_in[14],
                                          in_b);
    cudaEventRecord(evPackB, s2);
    // main: Bxq pack (needed by both first GEMMs)
    k_packA<<<dim3(256, 3), 256>>>((const float*)d_in[2], (const float*)d_in[3],
                                   (const float*)d_in[6]);

    // fork after packA: spatial branch on s1
    cudaEventRecord(evFork, 0);
    cudaStreamWaitEvent(s1, evFork, 0);

    // s1: xlr = x @ [Wl|Wr]  (N=1024), then fused GAT -> g_cat[:, :128]
    hgemm<1><<<dim3(8, 256), 256, SMEMSZ, s1>>>(x, p_Bxq, p_bxq,
                                                p_xlr, 1024, nullptr, 128,
                                                nullptr, nullptr, nullptr);
    k_gat<<<M_ / 8, 256, 0, s1>>>(gat_att, gat_b, lns_g, lns_b);
    cudaEventRecord(evJoin, s1);

    // main: qkv = x @ Wqkv (N=384) -> temporal chain
    hgemm<1><<<dim3(3, 256), 256, SMEMSZ>>>(x, p_Bxq + 1024 * 128, p_bxq + 1024,
                                            p_qkv, 384, nullptr, 128,
                                            nullptr, nullptr, nullptr);
    k_attn<<<(B_ * N_ * H_) / 4, 128>>>();
    cudaStreamWaitEvent(0, evPackB, 0);
    hgemm<4><<<dim3(1, 256), 256, SMEMSZ>>>(p_attno, p_Bout, out_b,
                                            p_x1, 128, nullptr, 128,
                                            x, lnt1_g, lnt1_b);
    hgemm<2><<<dim3(4, 256), 256, SMEMSZ>>>(p_x1, p_Bffn1, ffn_b1,
                                            p_hid, 512, nullptr, 128,
                                            nullptr, nullptr, nullptr);
    hgemm<5><<<dim3(1, 256), 256, SMEMSZ>>>(p_hid, p_Bffn2, ffn_b2,
                                            p_cat + 128, 256, nullptr, 512,
                                            p_x1, lnt2_g, lnt2_b);

    // join: fusion needs g_cat[:, :128] from the GAT branch
    cudaStreamWaitEvent(0, evJoin, 0);
    hgemm<6><<<dim3(1, 256), 256, SMEMSZ>>>(p_cat, p_Bfus, fus_b,
                                            out, 128, p_cat, 256,
                                            x, lnf_g, lnf_b);
}

// round 17
// speedup vs baseline: 1.0082x; 1.0082x over previous
#include <cuda_runtime.h>
#include <cuda_bf16.h>
#include <math.h>
#include <stdint.h>

#define B_  2
#define N_  1024
#define T_  8
#define D_  128
#define H_  4
#define E_  8192
#define M_  16384
#define MAXDEG 128

// ---------------- scratch (device globals) ----------------------------------
__device__ __align__(256) __nv_bfloat16 g_xlr[(size_t)M_ * 1024]; // bf16 [xl|xr]
__device__ __align__(256) float g_qkv[(size_t)M_ * 384];
__device__ __align__(256) float g_attno[(size_t)M_ * 128];
__device__ __align__(256) float g_x1[(size_t)M_ * 128];
__device__ __align__(256) float g_hid[(size_t)M_ * 512];
__device__ __align__(256) float g_cat[(size_t)M_ * 256];    // [x_sp | x_tp]
// packed tf32 weights, [n][k] layout
__device__ __align__(256) float g_Bxl[1024 * 128];          // [Wl|Wr]
__device__ __align__(256) float g_Bq[384 * 128];
__device__ __align__(256) float g_bias_q[384];
__device__ __align__(256) float g_Bout[128 * 128];
__device__ __align__(256) float g_Bffn1[512 * 128];
__device__ __align__(256) float g_Bffn2[128 * 512];
__device__ __align__(256) float g_Bfus[128 * 256];
// CSR
__device__ int g_deg[N_];
__device__ int g_csr[N_ * MAXDEG];

// ---------------- helpers ------------------------------------------------------
__device__ __forceinline__ float warp_sum(float v) {
#pragma unroll
    for (int o = 16; o; o >>= 1) v += __shfl_xor_sync(0xFFFFFFFFu, v, o);
    return v;
}
__device__ __forceinline__ uint32_t smem_u32(const void* p) {
    uint32_t a;
    asm("{ .reg .u64 t; cvta.to.shared.u64 t, %1; cvt.u32.u64 %0, t; }"
        : "=r"(a) : "l"(p));
    return a;
}
#define CP16(dst, src) \
    asm volatile("cp.async.cg.shared.global [%0], [%1], 16;" :: "r"(dst), "l"(src))
#define CVT_TF32(u, f) asm("cvt.rna.tf32.f32 %0, %1;" : "=r"(u) : "f"(f))

__device__ __forceinline__ void mma_tf32(float c[4], const uint32_t a[4],
                                         const uint32_t b[2]) {
    asm volatile(
        "mma.sync.aligned.m16n8k8.row.col.f32.tf32.tf32.f32 "
        "{%0,%1,%2,%3}, {%4,%5,%6,%7}, {%8,%9}, {%0,%1,%2,%3};"
        : "+f"(c[0]), "+f"(c[1]), "+f"(c[2]), "+f"(c[3])
        : "r"(a[0]), "r"(a[1]), "r"(a[2]), "r"(a[3]), "r"(b[0]), "r"(b[1]));
}

__device__ __forceinline__ float4 ln_compute(float4 v, const float* g, const float* b,
                                             int lane) {
    float mean = warp_sum(v.x + v.y + v.z + v.w) * (1.f / 128.f);
    float4 c = make_float4(v.x - mean, v.y - mean, v.z - mean, v.w - mean);
    float var = warp_sum(c.x * c.x + c.y * c.y + c.z * c.z + c.w * c.w) * (1.f / 128.f);
    float rs = rsqrtf(var + 1e-5f);
    float4 gv = *(const float4*)&g[lane * 4];
    float4 bv = *(const float4*)&b[lane * 4];
    return make_float4(c.x * rs * gv.x + bv.x, c.y * rs * gv.y + bv.y,
                       c.z * rs * gv.z + bv.z, c.w * rs * gv.w + bv.w);
}
__device__ __forceinline__ float4 bf4_to_f4(const __nv_bfloat16* p) {
    uint2 raw = *(const uint2*)p;
    __nv_bfloat162 p0 = *(__nv_bfloat162*)&raw.x;
    __nv_bfloat162 p1 = *(__nv_bfloat162*)&raw.y;
    float2 a = __bfloat1622float2(p0), b = __bfloat1622float2(p1);
    return make_float4(a.x, a.y, b.x, b.y);
}

// ---------------- CSR ------------------------------------------------------------
__global__ void k_csr0() {
    int i = blockIdx.x * blockDim.x + threadIdx.x;
    if (i < N_) { g_deg[i] = 1; g_csr[i * MAXDEG] = i; }
}
__global__ void k_scatter(const int* __restrict__ edges) {
    int e = blockIdx.x * blockDim.x + threadIdx.x;
    if (e >= E_) return;
    int s = edges[e], d = edges[E_ + e];
    int pos = atomicAdd(&g_deg[d], 1);
    if (pos < MAXDEG) g_csr[d * MAXDEG + pos] = s;
}

// ---------------- weight packing ---------------------------------------------------
// s1: Wl|Wr (tf32)
__global__ void k_packXL(const float* wl, const float* wr) {
    int job = blockIdx.y;
    int idx = blockIdx.x * 256 + threadIdx.x;
    if (idx >= 128 * 512) return;
    const float* W = job ? wr : wl;
    int coff = job ? 512 : 0;
    int k = idx / 512, n = idx % 512;
    uint32_t u;
    CVT_TF32(u, W[idx]);
    g_Bxl[(size_t)(coff + n) * 128 + k] = __uint_as_float(u);
}
// main: Wqkv + bias
__global__ void k_packQ(const float* inw, const float* in_b) {
    int idx = blockIdx.x * 256 + threadIdx.x;
    if (idx < 384) g_bias_q[idx] = in_b[idx];
    if (idx >= 128 * 384) return;
    int k = idx / 384, n = idx % 384;
    uint32_t u;
    CVT_TF32(u, inw[idx]);
    g_Bq[(size_t)n * 128 + k] = __uint_as_float(u);
}
// s2: late weights
__global__ void k_packB(const float* outw, const float* f1w, const float* f2w,
                        const float* fw) {
    int job = blockIdx.y;
    int idx = blockIdx.x * 256 + threadIdx.x;
    const float* W; float* Bo; int K, Nw;
    switch (job) {
        case 0: W = outw; Bo = g_Bout;  K = 128; Nw = 128; break;
        case 1: W = f1w;  Bo = g_Bffn1; K = 128; Nw = 512; break;
        case 2: W = f2w;  Bo = g_Bffn2; K = 512; Nw = 128; break;
        default:W = fw;   Bo = g_Bfus;  K = 256; Nw = 128; break;
    }
    if (idx >= K * Nw) return;
    int k = idx / Nw, n = idx % Nw;
    uint32_t u;
    CVT_TF32(u, W[idx]);
    Bo[(size_t)n * K + k] = __uint_as_float(u);
}

// ---------------- tf32 mma.sync GEMM (3-stage), templated epilogue ------------------
// MODE 1: +bias -> C1 ; MODE 2: +bias+GELU -> C1
// MODE 4/5: +bias, LN(xres + C) -> C1
// MODE 6: sigmoid gate; LN(g*xsp+(1-g)*xtp+xres) -> C1
// MODE 7: no bias, bf16 output -> (bf16*)C1 (stride s1 elements)
#define KP 20
#define APLANE (64 * KP)
#define BPLANE (128 * KP)
#define SMEMSZ ((APLANE + BPLANE) * 3 * 4)

template<int MODE>
__global__ void __launch_bounds__(256, 3) hgemm(
        const float* __restrict__ A, const float* __restrict__ Bp,
        const float* __restrict__ bias,
        float* __restrict__ C1, int s1,
        float* __restrict__ C2,
        int K,
        const float* __restrict__ xres,
        const float* __restrict__ lng, const float* __restrict__ lnb) {
    extern __shared__ float sm[];
    float* sA = sm;
    float* sB = sm + 3 * APLANE;
    int tid = threadIdx.x, wid = tid >> 5, lane = tid & 31;
    int wm = wid >> 2, wn = wid & 3;
    int rowBase = blockIdx.y * 64, colBase = blockIdx.x * 128;
    int nk = K >> 4;

    float acc[2][4][4];
#pragma unroll
    for (int i = 0; i < 2; i++)
#pragma unroll
        for (int j = 0; j < 4; j++)
#pragma unroll
            for (int q = 0; q < 4; q++) acc[i][j][q] = 0.f;

    int ar = tid >> 2, aq = tid & 3;
    int br = tid >> 1, bq = (tid & 1) * 2;
    const char* Asrc = (const char*)(A + (size_t)(rowBase + ar) * K + aq * 4);
    const char* Bsrc = (const char*)(Bp + (size_t)(colBase + br) * K + bq * 4);
    uint32_t dA = smem_u32(sA) + (uint32_t)(ar * KP + aq * 4) * 4;
    uint32_t dB = smem_u32(sB) + (uint32_t)(br * KP + bq * 4) * 4;

    auto ld = [&](int kt, int buf) {
        CP16(dA + buf * (APLANE * 4), Asrc + (size_t)kt * 64);
        CP16(dB + buf * (BPLANE * 4), Bsrc + (size_t)kt * 64);
        CP16(dB + buf * (BPLANE * 4) + 16, Bsrc + (size_t)kt * 64 + 16);
        asm volatile("cp.async.commit_group;" ::: "memory");
    };

    ld(0, 0);
    if (nk > 1) ld(1, 1);

    int fr = lane >> 2, fq = lane & 3;
    const float* awp = sA + (wm * 32 + fr) * KP + fq;
    const float* bwp = sB + (wn * 32 + fr) * KP + fq;

    for (int kt = 0; kt < nk; kt++) {
        int buf = kt % 3;
        if (kt + 1 < nk) asm volatile("cp.async.wait_group 1;" ::: "memory");
        else             asm volatile("cp.async.wait_group 0;" ::: "memory");
        __syncthreads();
        if (kt + 2 < nk) ld(kt + 2, (kt + 2) % 3);

        const float* aw = awp + buf * APLANE;
        const float* bw = bwp + buf * BPLANE;
#pragma unroll
        for (int k8 = 0; k8 < 2; k8++) {
            uint32_t ua[2][4], ub[4][2];
#pragma unroll
            for (int mi = 0; mi < 2; mi++) {
                const float* ap = aw + mi * (16 * KP) + k8 * 8;
                CVT_TF32(ua[mi][0], ap[0]);
                CVT_TF32(ua[mi][1], ap[8 * KP]);
                CVT_TF32(ua[mi][2], ap[4]);
                CVT_TF32(ua[mi][3], ap[8 * KP + 4]);
            }
#pragma unroll
            for (int ni = 0; ni < 4; ni++) {
                const float* bp = bw + ni * (8 * KP) + k8 * 8;
                ub[ni][0] = __float_as_uint(bp[0]);
                ub[ni][1] = __float_as_uint(bp[4]);
            }
#pragma unroll
            for (int mi = 0; mi < 2; mi++)
#pragma unroll
                for (int ni = 0; ni < 4; ni++)
                    mma_tf32(acc[mi][ni], ua[mi], ub[ni]);
        }
    }

    int fc2 = (lane & 3) * 2;
    if (MODE == 7) {
        __nv_bfloat16* Cb = (__nv_bfloat16*)C1;
#pragma unroll
        for (int mi = 0; mi < 2; mi++) {
            int r0 = rowBase + wm * 32 + mi * 16 + fr;
#pragma unroll
            for (int ni = 0; ni < 4; ni++) {
                int col = colBase + wn * 32 + ni * 8 + fc2;
                __nv_bfloat162 p0 = __floats2bfloat162_rn(acc[mi][ni][0], acc[mi][ni][1]);
                __nv_bfloat162 p1 = __floats2bfloat162_rn(acc[mi][ni][2], acc[mi][ni][3]);
                *(uint32_t*)&Cb[(size_t)r0 * s1 + col]       = *(uint32_t*)&p0;
                *(uint32_t*)&Cb[(size_t)(r0 + 8) * s1 + col] = *(uint32_t*)&p1;
            }
        }
    } else if (MODE == 1 || MODE == 2) {
#pragma unroll
        for (int mi = 0; mi < 2; mi++) {
            int r0 = rowBase + wm * 32 + mi * 16 + fr;
#pragma unroll
            for (int ni = 0; ni < 4; ni++) {
                int col = colBase + wn * 32 + ni * 8 + fc2;
                float b0 = bias[col], b1 = bias[col + 1];
                float v[4] = {acc[mi][ni][0] + b0, acc[mi][ni][1] + b1,
                              acc[mi][ni][2] + b0, acc[mi][ni][3] + b1};
                if (MODE == 2) {
#pragma unroll
                    for (int q = 0; q < 4; q++)
                        v[q] = 0.5f * v[q] * (1.f + erff(v[q] * 0.70710678118654752f));
                }
                *(float2*)&C1[(size_t)r0 * s1 + col]       = make_float2(v[0], v[1]);
                *(float2*)&C1[(size_t)(r0 + 8) * s1 + col] = make_float2(v[2], v[3]);
            }
        }
    } else {
        float* st = sm;
        __syncthreads();
#pragma unroll
        for (int mi = 0; mi < 2; mi++) {
            int rl = wm * 32 + mi * 16 + fr;
#pragma unroll
            for (int ni = 0; ni < 4; ni++) {
                int col = wn * 32 + ni * 8 + fc2;
                float b0 = bias[col], b1 = bias[col + 1];
                float v0 = acc[mi][ni][0] + b0, v1 = acc[mi][ni][1] + b1;
                float v2 = acc[mi][ni][2] + b0, v3 = acc[mi][ni][3] + b1;
                if (MODE == 6) {
                    v0 = 1.f / (1.f + __expf(-v0)); v1 = 1.f / (1.f + __expf(-v1));
                    v2 = 1.f / (1.f + __expf(-v2)); v3 = 1.f / (1.f + __expf(-v3));
                }
                *(float2*)&st[rl * 128 + col]       = make_float2(v0, v1);
                *(float2*)&st[(rl + 8) * 128 + col] = make_float2(v2, v3);
            }
        }
        __syncthreads();
#pragma unroll
        for (int r = 0; r < 8; r++) {
            int rl = wid * 8 + r;
            int grow = rowBase + rl;
            float4 cv = ((const float4*)(st + rl * 128))[lane];
            float4 v;
            if (MODE == 4 || MODE == 5) {
                float4 xv = *(const float4*)&xres[(size_t)grow * 128 + lane * 4];
                v = make_float4(cv.x + xv.x, cv.y + xv.y, cv.z + xv.z, cv.w + xv.w);
            } else {
                float4 xsp = *(const float4*)&C2[(size_t)grow * 256 + lane * 4];
                float4 xtp = *(const float4*)&C2[(size_t)grow * 256 + 128 + lane * 4];
                float4 xv  = *(const float4*)&xres[(size_t)grow * 128 + lane * 4];
                v = make_float4(cv.x * xsp.x + (1.f - cv.x) * xtp.x + xv.x,
                                cv.y * xsp.y + (1.f - cv.y) * xtp.y + xv.y,
                                cv.z * xsp.z + (1.f - cv.z) * xtp.z + xv.z,
                                cv.w * xsp.w + (1.f - cv.w) * xtp.w + xv.w);
            }
            float4 r4 = ln_compute(v, lng, lnb, lane);
            *(float4*)&C1[(size_t)grow * s1 + lane * 4] = r4;
        }
    }
}

// ---------------- fused GAT (bf16 xlr, online softmax) -----------------------------
__global__ void k_gat(const float* __restrict__ att, const float* __restrict__ gat_b,
                      const float* __restrict__ lg, const float* __restrict__ lb) {
    int w = (blockIdx.x * blockDim.x + threadIdx.x) >> 5;
    int lane = threadIdx.x & 31;
    if (w >= M_) return;
    int bn = w >> 3;
    int n = bn & (N_ - 1);
    int b = bn >> 10;
    int t = w & 7;

    const __nv_bfloat16* xrp = g_xlr + (size_t)w * 1024 + 512;
    float4 xr[4], av[4];
#pragma unroll
    for (int h = 0; h < 4; h++) {
        xr[h] = bf4_to_f4(xrp + h * 128 + lane * 4);
        av[h] = ((const float4*)att)[h * 32 + lane];
    }
    float4 acc[4];
#pragma unroll
    for (int h = 0; h < 4; h++) acc[h] = make_float4(0.f, 0.f, 0.f, 0.f);
    float m[4] = {-INFINITY, -INFINITY, -INFINITY, -INFINITY};
    float s[4] = {0.f, 0.f, 0.f, 0.f};

    int deg = g_deg[n];
    if (deg > MAXDEG) deg = MAXDEG;
    const int* clist = g_csr + n * MAXDEG;

    for (int i = 0; i < deg; i++) {
        int src = clist[i];
        const __nv_bfloat16* xlp = g_xlr + ((size_t)((b * N_ + src) * T_ + t)) * 1024;
        float4 xl[4];
        float lgt[4];
#pragma unroll
        for (int h = 0; h < 4; h++) {
            float4 a = bf4_to_f4(xlp + h * 128 + lane * 4);
            xl[h] = a;
            float v0 = a.x + xr[h].x; v0 = v0 > 0.f ? v0 : 0.2f * v0;
            float v1 = a.y + xr[h].y; v1 = v1 > 0.f ? v1 : 0.2f * v1;
            float v2 = a.z + xr[h].z; v2 = v2 > 0.f ? v2 : 0.2f * v2;
            float v3 = a.w + xr[h].w; v3 = v3 > 0.f ? v3 : 0.2f * v3;
            lgt[h] = warp_sum(av[h].x * v0 + av[h].y * v1 + av[h].z * v2 + av[h].w * v3);
        }
#pragma unroll
        for (int h = 0; h < 4; h++) {
            float nm = fmaxf(m[h], lgt[h]);
            float e0 = __expf(m[h] - nm);
            float e1 = __expf(lgt[h] - nm);
            s[h] = s[h] * e0 + e1;
            acc[h].x = acc[h].x * e0 + e1 * xl[h].x;
            acc[h].y = acc[h].y * e0 + e1 * xl[h].y;
            acc[h].z = acc[h].z * e0 + e1 * xl[h].z;
            acc[h].w = acc[h].w * e0 + e1 * xl[h].w;
            m[h] = nm;
        }
    }

    float4 o = make_float4(0.f, 0.f, 0.f, 0.f);
#pragma unroll
    for (int h = 0; h < 4; h++) {
        float r = 0.25f / s[h];
        o.x += acc[h].x * r; o.y += acc[h].y * r;
        o.z += acc[h].z * r; o.w += acc[h].w * r;
    }
    float4 gb = *(const float4*)&gat_b[lane * 4];
    o.x += gb.x; o.y += gb.y; o.z += gb.z; o.w += gb.w;

    float4 r4 = ln_compute(o, lg, lb, lane);
    *(float4*)&g_cat[(size_t)w * 256 + lane * 4] = r4;
}

// ---------------- temporal attention ------------------------------------------------
__global__ void k_attn() {
    int w = blockIdx.x * 4 + (threadIdx.x >> 5);
    int lane = threadIdx.x & 31;
    if (w >= (B_ * N_) * H_) return;
    int bn = w >> 2;
    int h = w & 3;
    float q[8], k[8], v[8];
#pragma unroll
    for (int t = 0; t < 8; t++) {
        size_t base = ((size_t)bn * 8 + t) * 384 + h * 32 + lane;
        q[t] = g_qkv[base];
        k[t] = g_qkv[base + 128];
        v[t] = g_qkv[base + 256];
    }
    const float scale = 0.17677669529663687f;
#pragma unroll
    for (int t = 0; t < 8; t++) {
        float sc[8];
#pragma unroll
        for (int s = 0; s < 8; s++) sc[s] = warp_sum(q[t] * k[s]) * scale;
        float mx = sc[0];
#pragma unroll
        for (int s = 1; s < 8; s++) mx = fmaxf(mx, sc[s]);
        float den = 0.f;
#pragma unroll
        for (int s = 0; s < 8; s++) { sc[s] = __expf(sc[s] - mx); den += sc[s]; }
        float inv = 1.f / den;
        float o = 0.f;
#pragma unroll
        for (int s = 0; s < 8; s++) o += sc[s] * v[s];
        g_attno[((size_t)bn * 8 + t) * D_ + h * 32 + lane] = o * inv;
    }
}

// ---------------- launch ---------------------------------------------------------------
extern "C" void kernel_launch(void* const* d_in, const int* in_sizes, int n_in,
                              void* d_out, int out_size) {
    const float* x      = (const float*)d_in[0];
    const int*   edges  = (const int*)  d_in[1];
    const float* gat_att= (const float*)d_in[4];
    const float* gat_b  = (const float*)d_in[5];
    const float* in_b   = (const float*)d_in[7];
    const float* out_b  = (const float*)d_in[9];
    const float* ffn_b1 = (const float*)d_in[11];
    const float* ffn_b2 = (const float*)d_in[13];
    const float* fus_b  = (const float*)d_in[15];
    const float* lns_g  = (const float*)d_in[16];
    const float* lns_b  = (const float*)d_in[17];
    const float* lnt1_g = (const float*)d_in[18];
    const float* lnt1_b = (const float*)d_in[19];
    const float* lnt2_g = (const float*)d_in[20];
    const float* lnt2_b = (const float*)d_in[21];
    const float* lnf_g  = (const float*)d_in[22];
    const float* lnf_b  = (const float*)d_in[23];
    float* out = (float*)d_out;

    float *p_qkv, *p_attno, *p_x1, *p_hid, *p_cat;
    float *p_bq, *p_Bxl, *p_Bq, *p_Bout, *p_Bffn1, *p_Bffn2, *p_Bfus;
    __nv_bfloat16* p_xlr;
    cudaGetSymbolAddress((void**)&p_xlr,   g_xlr);
    cudaGetSymbolAddress((void**)&p_Bxl,   g_Bxl);
    cudaGetSymbolAddress((void**)&p_qkv,   g_qkv);
    cudaGetSymbolAddress((void**)&p_attno, g_attno);
    cudaGetSymbolAddress((void**)&p_x1,    g_x1);
    cudaGetSymbolAddress((void**)&p_hid,   g_hid);
    cudaGetSymbolAddress((void**)&p_cat,   g_cat);
    cudaGetSymbolAddress((void**)&p_bq,    g_bias_q);
    cudaGetSymbolAddress((void**)&p_Bq,    g_Bq);
    cudaGetSymbolAddress((void**)&p_Bout,  g_Bout);
    cudaGetSymbolAddress((void**)&p_Bffn1, g_Bffn1);
    cudaGetSymbolAddress((void**)&p_Bffn2, g_Bffn2);
    cudaGetSymbolAddress((void**)&p_Bfus,  g_Bfus);

    cudaFuncSetAttribute(hgemm<1>, cudaFuncAttributeMaxDynamicSharedMemorySize, SMEMSZ);
    cudaFuncSetAttribute(hgemm<2>, cudaFuncAttributeMaxDynamicSharedMemorySize, SMEMSZ);
    cudaFuncSetAttribute(hgemm<4>, cudaFuncAttributeMaxDynamicSharedMemorySize, SMEMSZ);
    cudaFuncSetAttribute(hgemm<5>, cudaFuncAttributeMaxDynamicSharedMemorySize, SMEMSZ);
    cudaFuncSetAttribute(hgemm<6>, cudaFuncAttributeMaxDynamicSharedMemorySize, SMEMSZ);
    cudaFuncSetAttribute(hgemm<7>, cudaFuncAttributeMaxDynamicSharedMemorySize, SMEMSZ);

    static cudaStream_t s1 = nullptr, s2 = nullptr;
    static cudaEvent_t evRoot = nullptr, evJoin = nullptr, evPackB = nullptr;
    if (s1 == nullptr) {
        cudaStreamCreateWithFlags(&s1, cudaStreamNonBlocking);
        cudaStreamCreateWithFlags(&s2, cudaStreamNonBlocking);
        cudaEventCreateWithFlags(&evRoot, cudaEventDisableTiming);
        cudaEventCreateWithFlags(&evJoin, cudaEventDisableTiming);
        cudaEventCreateWithFlags(&evPackB, cudaEventDisableTiming);
    }

    // root fork: s1 and s2 join the capture first
    cudaEventRecord(evRoot, 0);
    cudaStreamWaitEvent(s1, evRoot, 0);
    cudaStreamWaitEvent(s2, evRoot, 0);

    // s1: fully independent spatial branch
    k_csr0<<<4, 256, 0, s1>>>();
    k_scatter<<<E_ / 256, 256, 0, s1>>>(edges);
    k_packXL<<<dim3(256, 2), 256, 0, s1>>>((const float*)d_in[2], (const float*)d_in[3]);
    // xlr = x @ [Wl|Wr]  (tf32, bf16 output) -> fused GAT -> g_cat[:, :128]
    hgemm<7><<<dim3(8, 256), 256, SMEMSZ, s1>>>(x, p_Bxl, nullptr,
                                                (float*)p_xlr, 1024, nullptr, 128,
                                                nullptr, nullptr, nullptr);
    k_gat<<<M_ / 8, 256, 0, s1>>>(gat_att, gat_b, lns_g, lns_b);
    cudaEventRecord(evJoin, s1);

    // s2: late weights
    k_packB<<<dim3(256, 4), 256, 0, s2>>>((const float*)d_in[8], (const float*)d_in[10],
                                          (const float*)d_in[12], (const float*)d_in[14]);
    cudaEventRecord(evPackB, s2);

    // main: qkv pack (incl. its bias) -> temporal chain
    k_packQ<<<192, 256>>>((const float*)d_in[6], in_b);
    hgemm<1><<<dim3(3, 256), 256, SMEMSZ>>>(x, p_Bq, p_bq,
                                            p_qkv, 384, nullptr, 128,
                                            nullptr, nullptr, nullptr);
    k_attn<<<(B_ * N_ * H_) / 4, 128>>>();
    cudaStreamWaitEvent(0, evPackB, 0);
    hgemm<4><<<dim3(1, 256), 256, SMEMSZ>>>(p_attno, p_Bout, out_b,
                                            p_x1, 128, nullptr, 128,
                                            x, lnt1_g, lnt1_b);
    hgemm<2><<<dim3(4, 256), 256, SMEMSZ>>>(p_x1, p_Bffn1, ffn_b1,
                                            p_hid, 512, nullptr, 128,
                                            nullptr, nullptr, nullptr);
    hgemm<5><<<dim3(1, 256), 256, SMEMSZ>>>(p_hid, p_Bffn2, ffn_b2,
                                            p_cat + 128, 256, nullptr, 512,
                                            p_x1, lnt2_g, lnt2_b);

    // join: fusion needs g_cat[:, :128] from the GAT branch
    cudaStreamWaitEvent(0, evJoin, 0);
    hgemm<6><<<dim3(1, 256), 256, SMEMSZ>>>(p_cat, p_Bfus, fus_b,
                                            out, 128, p_cat, 256,
                                            x, lnf_g, lnf_b);
}